// round 11
// baseline (speedup 1.0000x reference)
#include <cuda_runtime.h>

#define NA 192
#define TT 80
#define NC 5
#define ISLICE 12
#define NPAIR ((size_t)NA * NA)

// Precomputed world circle centers: (wx, wy, wx^2+wy^2, 0) for all (t, agent, circle).
// 80*192*5*16B = 245 KB — L2-resident.
__device__ float4 g_sw[TT * NA * NC];

__global__ __launch_bounds__(NA) void precompute_kernel(
    const float4* __restrict__ traj,   // [NA*T] (x,y,hx,hy)
    const float4* __restrict__ cent)   // [NA*NC] (cx,cy,1,0)
{
    const int t = blockIdx.x;
    const int a = threadIdx.x;
    float4 tr = traj[a * TT + t];
    float hx = tr.z, hy = tr.w;
    float inv = rsqrtf(fmaf(hx, hx, hy * hy));
    hx *= inv;
    hy *= inv;
    float4* dst = g_sw + ((size_t)t * NA + a) * NC;
#pragma unroll
    for (int c = 0; c < NC; c++) {
        float4 cc = cent[a * NC + c];
        float wx = tr.x + hx * cc.x - hy * cc.y;
        float wy = tr.y + hy * cc.x + hx * cc.y;
        dst[c] = make_float4(wx, wy, fmaf(wx, wx, wy * wy), 0.0f);
    }
}

// Block: 192 threads, j = tid. Grid: (T, NA/ISLICE) = (80, 16). No smem, no syncs.
//   d^2 = s_i[c] + fma(wix, uj[d], fma(wiy, vj[d], sj[d])),  uj=-2wjx, vj=-2wjy.
__global__ __launch_bounds__(NA, 8) void vehcoll_kernel(
    const float*  __restrict__ pd,     // [NA*NA]
    const int*    __restrict__ offd,   // [NA*NA] bool upcast to int32
    float* __restrict__ out_pen,       // [T*NA*NA]
    float* __restrict__ out_mask)      // [T*NA*NA] (0.0/1.0)
{
    const int t   = blockIdx.x;
    const int j   = threadIdx.x;
    const float4* __restrict__ swt = g_sw + (size_t)t * NA * NC;

    // per-thread j-column constants
    float uj[NC], vj[NC], sj[NC];
#pragma unroll
    for (int d = 0; d < NC; d++) {
        float4 w = __ldg(&swt[j * NC + d]);
        uj[d] = -2.0f * w.x;
        vj[d] = -2.0f * w.y;
        sj[d] = w.z;
    }

    const int    ibase = blockIdx.y * ISLICE;
    const size_t tbase = (size_t)t * NPAIR + (size_t)ibase * NA + j;
    const int    pbase = ibase * NA + j;

#pragma unroll 4
    for (int ii = 0; ii < ISLICE; ii++) {
        float minv = 3.4e38f;
#pragma unroll
        for (int c = 0; c < NC; c++) {
            // warp-uniform address -> single-sector L1 broadcast
            float4 wi = __ldg(&swt[(ibase + ii) * NC + c]);
            float p0 = fmaf(wi.x, uj[0], fmaf(wi.y, vj[0], sj[0]));
            float p1 = fmaf(wi.x, uj[1], fmaf(wi.y, vj[1], sj[1]));
            float p2 = fmaf(wi.x, uj[2], fmaf(wi.y, vj[2], sj[2]));
            float p3 = fmaf(wi.x, uj[3], fmaf(wi.y, vj[3], sj[3]));
            float p4 = fmaf(wi.x, uj[4], fmaf(wi.y, vj[4], sj[4]));
            float m  = fminf(fminf(fminf(p0, p1), fminf(p2, p3)), p4);
            minv = fminf(minv, wi.z + m);  // + s_i[c]
        }
        const float dd = sqrtf(fmaxf(minv, 0.0f));
        const float p  = pd[pbase + ii * NA];
        const float pen = 1.0f - __fdividef(dd, p);
        const bool  col = (dd <= p) && (offd[pbase + ii * NA] != 0);

        out_pen [tbase + (size_t)ii * NA] = pen;
        out_mask[tbase + (size_t)ii * NA] = col ? 1.0f : 0.0f;
    }
}

extern "C" void kernel_launch(void* const* d_in, const int* in_sizes, int n_in,
                              void* d_out, int out_size) {
    const float4* traj = (const float4*)d_in[0];        // [192,80,4]
    const float4* cent = (const float4*)d_in[1];        // [192,5,4]
    const float*  pd   = (const float*)d_in[2];         // [192,192]
    const int*    offd = (const int*)d_in[3];           // [192,192] int32

    float* out_pen  = (float*)d_out;
    float* out_mask = out_pen + (size_t)TT * NPAIR;

    precompute_kernel<<<TT, NA>>>(traj, cent);
    dim3 grid(TT, NA / ISLICE);
    vehcoll_kernel<<<grid, NA>>>(pd, offd, out_pen, out_mask);
}

// round 12
// speedup vs baseline: 1.1954x; 1.1954x over previous
#include <cuda_runtime.h>

#define NA 192
#define TT 80
#define NC 5
#define TILE 32
#define NTP 21            // unordered tile pairs of 6 tiles (ti <= tj)
#define NPAIR ((size_t)NA * NA)

// world circle centers (wx, wy, wx^2+wy^2, 0) for all (t, agent, circle); 245 KB, L2-resident
__device__ float4 g_sw[TT * NA * NC];

__constant__ unsigned char c_ti[NTP] = {0,0,0,0,0,0,1,1,1,1,1,2,2,2,2,3,3,3,4,4,5};
__constant__ unsigned char c_tj[NTP] = {0,1,2,3,4,5,1,2,3,4,5,2,3,4,5,3,4,5,4,5,5};

__global__ __launch_bounds__(NA) void precompute_kernel(
    const float4* __restrict__ traj,   // [NA*T] (x,y,hx,hy)
    const float4* __restrict__ cent)   // [NA*NC] (cx,cy,1,0)
{
    const int t = blockIdx.x;
    const int a = threadIdx.x;
    float4 tr = traj[a * TT + t];
    float hx = tr.z, hy = tr.w;
    float inv = rsqrtf(fmaf(hx, hx, hy * hy));
    hx *= inv;
    hy *= inv;
    float4* dst = g_sw + ((size_t)t * NA + a) * NC;
#pragma unroll
    for (int c = 0; c < NC; c++) {
        float4 cc = cent[a * NC + c];
        float wx = tr.x + hx * cc.x - hy * cc.y;
        float wy = tr.y + hy * cc.x + hx * cc.y;
        dst[c] = make_float4(wx, wy, fmaf(wx, wx, wy * wy), 0.0f);
    }
}

// Grid: (T, 21 tile-pairs). Block: 256 threads = 8 warps.
// Warp ty handles i-rows [ti*32 + ty*4, +4); lane owns j = tj*32 + lane.
// Off-diagonal tile pairs write the mirrored (j,i) half via an smem transpose.
__global__ __launch_bounds__(256, 6) void vehcoll_kernel(
    const float*  __restrict__ pd,     // [NA*NA]
    const int*    __restrict__ offd,   // [NA*NA] bool upcast to int32
    float* __restrict__ out_pen,       // [T*NA*NA]
    float* __restrict__ out_mask)      // [T*NA*NA] (0.0/1.0)
{
    __shared__ float spen [TILE][TILE + 1];
    __shared__ float smask[TILE][TILE + 1];

    const int t    = blockIdx.x;
    const int ti   = c_ti[blockIdx.y];
    const int tj   = c_tj[blockIdx.y];
    const int lane = threadIdx.x & 31;
    const int ty   = threadIdx.x >> 5;
    const int j    = tj * TILE + lane;

    const float4* __restrict__ swt = g_sw + (size_t)t * NA * NC;

    // per-thread j-column constants
    float uj[NC], vj[NC], sj[NC];
#pragma unroll
    for (int d = 0; d < NC; d++) {
        float4 w = __ldg(&swt[j * NC + d]);
        uj[d] = -2.0f * w.x;
        vj[d] = -2.0f * w.y;
        sj[d] = w.z;
    }

    const int    il0   = ty * 4;            // first i-local of this warp
    const size_t tbase = (size_t)t * NPAIR;

#pragma unroll
    for (int k = 0; k < 4; k++) {
        const int il = il0 + k;
        const int i  = ti * TILE + il;
        float minv = 3.4e38f;
#pragma unroll
        for (int c = 0; c < NC; c++) {
            float4 wi = __ldg(&swt[i * NC + c]);   // warp-uniform broadcast
            float p0 = fmaf(wi.x, uj[0], fmaf(wi.y, vj[0], sj[0]));
            float p1 = fmaf(wi.x, uj[1], fmaf(wi.y, vj[1], sj[1]));
            float p2 = fmaf(wi.x, uj[2], fmaf(wi.y, vj[2], sj[2]));
            float p3 = fmaf(wi.x, uj[3], fmaf(wi.y, vj[3], sj[3]));
            float p4 = fmaf(wi.x, uj[4], fmaf(wi.y, vj[4], sj[4]));
            float m  = fminf(fminf(fminf(p0, p1), fminf(p2, p3)), p4);
            minv = fminf(minv, wi.z + m);  // + s_i[c]
        }
        const float dd = sqrtf(fmaxf(minv, 0.0f));
        const int   pidx = i * NA + j;
        const float p   = pd[pidx];
        const float pen = 1.0f - __fdividef(dd, p);
        const float msk = ((dd <= p) && (offd[pidx] != 0)) ? 1.0f : 0.0f;

        out_pen [tbase + pidx] = pen;     // coalesced: j = lane-consecutive
        out_mask[tbase + pidx] = msk;

        spen [lane][il] = pen;            // stride-33 rows: conflict-free
        smask[lane][il] = msk;
    }

    if (ti != tj) {
        __syncthreads();
        // mirrored half: out[t, j', i'] with i' = ti*32 + lane (coalesced)
#pragma unroll
        for (int k = 0; k < 4; k++) {
            const int jl = il0 + k;
            const size_t qidx = tbase + (size_t)(tj * TILE + jl) * NA + ti * TILE + lane;
            out_pen [qidx] = spen [jl][lane];
            out_mask[qidx] = smask[jl][lane];
        }
    }
}

extern "C" void kernel_launch(void* const* d_in, const int* in_sizes, int n_in,
                              void* d_out, int out_size) {
    const float4* traj = (const float4*)d_in[0];        // [192,80,4]
    const float4* cent = (const float4*)d_in[1];        // [192,5,4]
    const float*  pd   = (const float*)d_in[2];         // [192,192]
    const int*    offd = (const int*)d_in[3];           // [192,192] int32

    float* out_pen  = (float*)d_out;
    float* out_mask = out_pen + (size_t)TT * NPAIR;

    precompute_kernel<<<TT, NA>>>(traj, cent);
    dim3 grid(TT, NTP);
    vehcoll_kernel<<<grid, 256>>>(pd, offd, out_pen, out_mask);
}

// round 16
// speedup vs baseline: 1.4830x; 1.2405x over previous
#include <cuda_runtime.h>

#define NA 192
#define TT 80
#define NC 5
#define TILE 32
#define NTP 21            // unordered tile pairs of 6 tiles (ti <= tj)
#define NPAIR ((size_t)NA * NA)

__constant__ unsigned char c_ti[NTP] = {0,0,0,0,0,0,1,1,1,1,1,2,2,2,2,3,3,3,4,4,5};
__constant__ unsigned char c_tj[NTP] = {0,1,2,3,4,5,1,2,3,4,5,2,3,4,5,3,4,5,4,5,5};

// Grid: (T, 21 tile-pairs). Block: 256 threads = 8 warps. Single fused kernel.
// Prologue: threads 0-31 build tile-i world points (wx,wy,s) in swi;
//           threads 32-63 build tile-j folded constants (-2wx,-2wy,s) in swj.
// Main: warp ty handles i-rows [ty*4, ty*4+4); lane owns j-column.
// Off-diagonal tile pairs write the mirrored (j,i) half via an smem transpose.
__global__ __launch_bounds__(256, 6) void vehcoll_kernel(
    const float4* __restrict__ traj,   // [NA*T] (x,y,hx,hy)
    const float4* __restrict__ cent,   // [NA*NC] (cx,cy,1,0)
    const float*  __restrict__ pd,     // [NA*NA]
    const int*    __restrict__ offd,   // [NA*NA] bool upcast to int32
    float* __restrict__ out_pen,       // [T*NA*NA]
    float* __restrict__ out_mask)      // [T*NA*NA] (0.0/1.0)
{
    __shared__ float4 swi[TILE * NC];          // (wx, wy, s, 0) for tile i
    __shared__ float4 swj[TILE * NC];          // (-2wx, -2wy, s, 0) for tile j
    __shared__ float  spen [TILE][TILE + 1];
    __shared__ float  smask[TILE][TILE + 1];

    const int t    = blockIdx.x;
    const int ti   = c_ti[blockIdx.y];
    const int tj   = c_tj[blockIdx.y];
    const int tid  = threadIdx.x;
    const int lane = tid & 31;
    const int ty   = tid >> 5;

    // ---- Prologue: 64 threads compute the two tiles' circle points ----
    if (tid < 64) {
        const bool  isj = (tid >= 32);
        const int   a   = (isj ? tj : ti) * TILE + lane;
        float4 tr = traj[a * TT + t];
        float hx = tr.z, hy = tr.w;
        float inv = rsqrtf(fmaf(hx, hx, hy * hy));
        hx *= inv;
        hy *= inv;
        float4* dst = (isj ? swj : swi) + lane * NC;
#pragma unroll
        for (int c = 0; c < NC; c++) {
            float4 cc = cent[a * NC + c];
            float wx = tr.x + hx * cc.x - hy * cc.y;
            float wy = tr.y + hy * cc.x + hx * cc.y;
            float s  = fmaf(wx, wx, wy * wy);
            dst[c] = isj ? make_float4(-2.0f * wx, -2.0f * wy, s, 0.0f)
                         : make_float4(wx, wy, s, 0.0f);
        }
    }
    __syncthreads();

    // ---- per-thread j-column constants ----
    const int j = tj * TILE + lane;
    float uj[NC], vj[NC], sj[NC];
#pragma unroll
    for (int d = 0; d < NC; d++) {
        float4 w = swj[lane * NC + d];
        uj[d] = w.x;
        vj[d] = w.y;
        sj[d] = w.z;
    }

    const int    il0   = ty * 4;            // first i-local of this warp
    const size_t tbase = (size_t)t * NPAIR;

#pragma unroll
    for (int k = 0; k < 4; k++) {
        const int il = il0 + k;
        const int i  = ti * TILE + il;
        float minv = 3.4e38f;
#pragma unroll
        for (int c = 0; c < NC; c++) {
            float4 wi = swi[il * NC + c];   // broadcast LDS.128 (warp-uniform)
            float p0 = fmaf(wi.x, uj[0], fmaf(wi.y, vj[0], sj[0]));
            float p1 = fmaf(wi.x, uj[1], fmaf(wi.y, vj[1], sj[1]));
            float p2 = fmaf(wi.x, uj[2], fmaf(wi.y, vj[2], sj[2]));
            float p3 = fmaf(wi.x, uj[3], fmaf(wi.y, vj[3], sj[3]));
            float p4 = fmaf(wi.x, uj[4], fmaf(wi.y, vj[4], sj[4]));
            float m  = fminf(fminf(fminf(p0, p1), fminf(p2, p3)), p4);
            minv = fminf(minv, wi.z + m);  // + s_i[c]
        }
        const float dd = sqrtf(fmaxf(minv, 0.0f));
        const int   pidx = i * NA + j;
        const float p   = pd[pidx];
        const float pen = 1.0f - __fdividef(dd, p);
        const float msk = ((dd <= p) && (offd[pidx] != 0)) ? 1.0f : 0.0f;

        out_pen [tbase + pidx] = pen;     // coalesced: j = lane-consecutive
        out_mask[tbase + pidx] = msk;

        spen [lane][il] = pen;            // stride-33 rows: conflict-free
        smask[lane][il] = msk;
    }

    if (ti != tj) {
        __syncthreads();
        // mirrored half: out[t, j', i'] with i' = ti*32 + lane (coalesced)
#pragma unroll
        for (int k = 0; k < 4; k++) {
            const int jl = il0 + k;
            const size_t qidx = tbase + (size_t)(tj * TILE + jl) * NA + ti * TILE + lane;
            out_pen [qidx] = spen [jl][lane];
            out_mask[qidx] = smask[jl][lane];
        }
    }
}

extern "C" void kernel_launch(void* const* d_in, const int* in_sizes, int n_in,
                              void* d_out, int out_size) {
    const float4* traj = (const float4*)d_in[0];        // [192,80,4]
    const float4* cent = (const float4*)d_in[1];        // [192,5,4]
    const float*  pd   = (const float*)d_in[2];         // [192,192]
    const int*    offd = (const int*)d_in[3];           // [192,192] int32

    float* out_pen  = (float*)d_out;
    float* out_mask = out_pen + (size_t)TT * NPAIR;

    dim3 grid(TT, NTP);
    vehcoll_kernel<<<grid, 256>>>(traj, cent, pd, offd, out_pen, out_mask);
}